// round 16
// baseline (speedup 1.0000x reference)
#include <cuda_runtime.h>
#include <math.h>
#include <float.h>

#define BB 16
#define NN 1024
#define KK 16
#define MSGD 128
#define PI_F 3.14159265358979323846f
#define TWOPI_F 6.28318530717958647692f
#define INV_TWOPI_F 0.15915494309189533577f
#define EPS_F 1e-8f

// ---------------- device scratch ----------------
__device__ __align__(16) float g_lvpack[BB*NN*8];   // px,py,pz,e,pt,rap,phi,mask
__device__ int   g_idx[BB*NN*KK];
__device__ __align__(16) float g_u[BB*NN*MSGD];
__device__ __align__(16) float g_v[BB*NN*MSGD];
__device__ __align__(16) float g_R[BB*NN*MSGD];
__device__ __align__(16) float g_cnt[BB*NN];
__device__ float g_Pp[BB*32*MSGD];
__device__ float g_nbp[BB*32];
__device__ float g_M[8*128];                        // se_w1 @ w_e2 (precomputed)

__device__ __forceinline__ float wrap_dphi(float x) {
    float xp = x + PI_F;
    return xp - floorf(xp * INV_TWOPI_F) * TWOPI_F - PI_F;
}

// packed f32x2 helpers
__device__ __forceinline__ unsigned long long pk2(float lo, float hi) {
    unsigned long long r;
    asm("mov.b64 %0, {%1, %2};" : "=l"(r) : "f"(lo), "f"(hi));
    return r;
}
__device__ __forceinline__ void upk2(unsigned long long v, float& lo, float& hi) {
    asm("mov.b64 {%0, %1}, %2;" : "=f"(lo), "=f"(hi) : "l"(v));
}
__device__ __forceinline__ void ffma2(unsigned long long& acc,
                                      unsigned long long a, unsigned long long b) {
    asm("fma.rn.f32x2 %0, %1, %2, %0;" : "+l"(acc) : "l"(a), "l"(b));
}

// ---------------- kA: mask detect + lv prep + knn (bitonic warm-up + ballot pops) ----------------
__global__ void __launch_bounds__(256, 6)
kA_prep_knn(const float* __restrict__ pts, const float* __restrict__ lvs,
            const void* __restrict__ mask,
            const float* __restrict__ se_w1, const float* __restrict__ w_e2) {
    __shared__ float se[NN], sp[NN];
    __shared__ int s_mode;
    int t = threadIdx.x;
    int b = blockIdx.x >> 6;
    int chunk = blockIdx.x & 63;          // 16 nodes per block

    // block 0: precompute M = se_w1 @ w_e2 (weights-only, 8x128)
    if (blockIdx.x == 0) {
        int k = t & 127, ih = t >> 7;
#pragma unroll
        for (int ii = 0; ii < 4; ii++) {
            int i = ih * 4 + ii;
            float s = 0.f;
#pragma unroll 4
            for (int c = 0; c < 128; c++)
                s += se_w1[i * 128 + c] * w_e2[c * 128 + k];
            g_M[i * 128 + k] = s;
        }
    }

    if (t == 0) {
        const unsigned int* mw = (const unsigned int*)mask;
        int allf = 1, alli = 1;
        for (int q = 0; q < 64; q++) {
            unsigned int wv = mw[q];
            if (!(wv == 0u || wv == 0x3F800000u)) allf = 0;
            if (!(wv == 0u || wv == 1u))          alli = 0;
        }
        s_mode = allf ? 0 : (alli ? 1 : 2);
    }
    for (int q = t; q < NN; q += 256) {
        se[q] = pts[b * 2 * NN + q];
        sp[q] = pts[b * 2 * NN + NN + q];
    }
    __syncthreads();

    if (t < 16) {
        int gid = b * NN + chunk * 16 + t;
        int n = gid & (NN - 1);
        int mode = s_mode;
        float m;
        if (mode == 0)      m = (((const float*)mask)[gid] != 0.f) ? 1.f : 0.f;
        else if (mode == 1) m = (((const int*)mask)[gid] != 0) ? 1.f : 0.f;
        else                m = (((const unsigned char*)mask)[gid] != 0) ? 1.f : 0.f;
        const float* base = lvs + b * 4 * NN + n;
        float px = base[0], py = base[NN], pz = base[2 * NN], e = base[3 * NN];
        float pt  = sqrtf(px * px + py * py);
        float rap = 0.5f * log1pf(2.f * pz / fmaxf(e - pz, 1e-20f));
        float phi = atan2f(py, px);
        float4* o = (float4*)(g_lvpack + gid * 8);
        o[0] = make_float4(px, py, pz, e);
        o[1] = make_float4(pt, rap, phi, m);
    }

    int w = t >> 5, lane = t & 31;
#pragma unroll 1
    for (int nn = 0; nn < 2; nn++) {
        int i = chunk * 16 + w * 2 + nn;
        float ei = se[i], pii = sp[i];

        // --- warm-up: bitonic sort first 32 candidates by (d, j) lex ascending ---
        float d;
        int   jv = lane;
        {
            float de = ei - se[lane];
            float dp = wrap_dphi(pii - sp[lane]);
            d = de * de + dp * dp;
        }
#pragma unroll
        for (int kk = 2; kk <= 32; kk <<= 1) {
#pragma unroll
            for (int jj = kk >> 1; jj > 0; jj >>= 1) {
                float od = __shfl_xor_sync(0xffffffffu, d, jj);
                int   oj = __shfl_xor_sync(0xffffffffu, jv, jj);
                bool up = ((lane & kk) == 0);
                bool lower = ((lane & jj) == 0);
                bool smaller = (od < d) || (od == d && oj < jv);
                bool keepOther = (up == lower) ? smaller : !smaller;
                if (keepOther) { d = od; jv = oj; }
            }
        }
        float dslot = d;
        int   jslot = jv;
        float thr = __shfl_sync(0xffffffffu, dslot, 15);

        // --- main scan with tight threshold ---
#pragma unroll 1
        for (int j0 = 32; j0 < NN; j0 += 32) {
            int j = j0 + lane;
            float de = ei - se[j];
            float dp = wrap_dphi(pii - sp[j]);
            float dd = de * de + dp * dp;
            unsigned m = __ballot_sync(0xffffffffu, dd < thr);
            while (m) {
                int src = __ffs(m) - 1; m &= m - 1;
                float dv = __shfl_sync(0xffffffffu, dd, src);
                if (!(dv < thr)) continue;
                int jn = j0 + src;
                float prevd = __shfl_up_sync(0xffffffffu, dslot, 1);
                int   prevj = __shfl_up_sync(0xffffffffu, jslot, 1);
                bool pg = (lane > 0) && (prevd > dv);
                if (dslot > dv) {
                    dslot = pg ? prevd : dv;
                    jslot = pg ? prevj : jn;
                }
                thr = __shfl_sync(0xffffffffu, dslot, 15);
            }
        }
        if (lane < 16) g_idx[(b * NN + i) * KK + lane] = jslot;
    }
}

// ---------------- k3: node features -> u, v (64 nodes/block, 2 blocks/SM) ----------------
__global__ void __launch_bounds__(256, 2)
k3_nodeuv(const float* __restrict__ fts,
          const float* __restrict__ bn1_s, const float* __restrict__ bn1_b,
          const float* __restrict__ w_node,
          const float* __restrict__ bn2_s, const float* __restrict__ bn2_b,
          const float* __restrict__ w_e1) {
    extern __shared__ float sm3[];
    float* ra_s = sm3;               // [64 k][68]
    float* rb_s = ra_s + 64 * 68;    // [64 k][68]
    float* w_s  = rb_s + 64 * 68;    // [64 k][132]; phase-1 overlay:
    float* a_s  = w_s;               // [32 c][64 n]
    float* wn_s = w_s + 2048;        // [64 o][32 c]

    int t   = threadIdx.x;
    int gn0 = blockIdx.x * 64;
    int b   = gn0 >> 10;
    int n0  = gn0 & (NN - 1);

    for (int q = t; q < 2048; q += 256) {
        int c = q >> 6, n = q & 63;
        float v = fts[(b * 32 + c) * NN + n0 + n];
        a_s[q] = fmaxf(v * __ldg(bn1_s + c) + __ldg(bn1_b + c), 0.f);
    }
    for (int q = t; q < 2048; q += 256) wn_s[q] = w_node[q];
    __syncthreads();

    {
        int og = t >> 6, node = t & 63;
        float av[32];
#pragma unroll
        for (int c = 0; c < 32; c++) av[c] = a_s[c * 64 + node];
#pragma unroll
        for (int oo = 0; oo < 16; oo++) {
            int o = og * 16 + oo;
            const float* wr = wn_s + o * 32;
            float nv = 0.f;
#pragma unroll
            for (int c = 0; c < 32; c++) nv += wr[c] * av[c];
            ra_s[o * 68 + node] = fmaxf(nv * __ldg(bn2_s + o)      + __ldg(bn2_b + o), 0.f);
            rb_s[o * 68 + node] = fmaxf(nv * __ldg(bn2_s + 64 + o) + __ldg(bn2_b + 64 + o), 0.f);
        }
    }
    __syncthreads();

    int cg = t >> 4, ng = t & 15;
#pragma unroll
    for (int pass = 0; pass < 2; pass++) {
        const float* rs = pass ? rb_s : ra_s;
        float* gout = pass ? g_v : g_u;
        for (int q = t; q < 2048; q += 256) {
            int ch = q >> 4, k4 = (q & 15) << 2;
            float4 w4 = *(const float4*)(w_e1 + ch * 132 + pass * 64 + k4);
            w_s[(k4 + 0) * 132 + ch] = w4.x;
            w_s[(k4 + 1) * 132 + ch] = w4.y;
            w_s[(k4 + 2) * 132 + ch] = w4.z;
            w_s[(k4 + 3) * 132 + ch] = w4.w;
        }
        __syncthreads();
        unsigned long long acc[4][4];
#pragma unroll
        for (int i = 0; i < 4; i++)
#pragma unroll
            for (int j = 0; j < 4; j++) acc[i][j] = 0ull;
#pragma unroll 4
        for (int k = 0; k < 64; k++) {
            float4 wa = *(const float4*)(w_s + k * 132 + cg * 8);
            float4 wb = *(const float4*)(w_s + k * 132 + cg * 8 + 4);
            float4 r4 = *(const float4*)(rs  + k * 68 + ng * 4);
            unsigned long long wp[4] = {pk2(wa.x, wa.y), pk2(wa.z, wa.w),
                                        pk2(wb.x, wb.y), pk2(wb.z, wb.w)};
            unsigned long long rd[4] = {pk2(r4.x, r4.x), pk2(r4.y, r4.y),
                                        pk2(r4.z, r4.z), pk2(r4.w, r4.w)};
#pragma unroll
            for (int i = 0; i < 4; i++)
#pragma unroll
                for (int j = 0; j < 4; j++) ffma2(acc[i][j], wp[i], rd[j]);
        }
#pragma unroll
        for (int j = 0; j < 4; j++) {
            float v0, v1, v2, v3, v4, v5, v6, v7;
            upk2(acc[0][j], v0, v1); upk2(acc[1][j], v2, v3);
            upk2(acc[2][j], v4, v5); upk2(acc[3][j], v6, v7);
            float* op = gout + (gn0 + ng * 4 + j) * MSGD + cg * 8;
            *(float4*)op       = make_float4(v0, v1, v2, v3);
            *(float4*)(op + 4) = make_float4(v4, v5, v6, v7);
        }
        __syncthreads();
    }
}

// ---------------- k4: fused edge kernel -> R + block-partial pool ----------------
__global__ void __launch_bounds__(512)
k4_edge(const float* __restrict__ w_e1,
        const float* __restrict__ bn2_s, const float* __restrict__ bn2_b,
        const float* __restrict__ bn3_s, const float* __restrict__ bn3_b) {
    __shared__ int   js[512];
    __shared__ float rlv[512 * 4];
    __shared__ float vld[512];
    __shared__ float wc4[128 * 5];
    __shared__ float s3s[128], b3s[128];
    __shared__ float s2l[4], b2l[4];
    __shared__ float R_s[32 * 132];
    __shared__ float cpart[32];
    int t  = threadIdx.x;
    int b  = blockIdx.x >> 5;
    int blk = blockIdx.x & 31;
    int i0 = blk * 32;

    js[t] = g_idx[(b * NN + i0) * KK + t];
    if (t < 128) {
#pragma unroll
        for (int f = 0; f < 4; f++) wc4[t * 5 + f] = w_e1[t * 132 + 128 + f];
        s3s[t] = bn3_s[t]; b3s[t] = bn3_b[t];
    }
    if (t < 4) { s2l[t] = bn2_s[128 + t]; b2l[t] = bn2_b[128 + t]; }
    __syncthreads();

    {
        int e = t;
        int i = i0 + (e >> 4), j = js[e];
        const float4* Li = (const float4*)(g_lvpack + (b * NN + i) * 8);
        const float4* Lj = (const float4*)(g_lvpack + (b * NN + j) * 8);
        float4 A0 = Li[0], A1 = Li[1], B0 = Lj[0], B1 = Lj[1];
        float pti = A1.x, ptj = B1.x;
        float ptmin = fminf(pti, ptj);
        float dphi = wrap_dphi(A1.z - B1.z);
        float drap  = A1.y - B1.y;
        float delta = sqrtf(drap * drap + dphi * dphi);
        float lndelta = logf(fmaxf(delta, EPS_F));
        float lnkt    = logf(fmaxf(ptmin * delta, EPS_F));
        float lnz     = logf(fmaxf(ptmin / fmaxf(pti + ptj, EPS_F), EPS_F));
        float sx = A0.x + B0.x, sy = A0.y + B0.y, sz = A0.z + B0.z, s4 = A0.w + B0.w;
        float lnm2 = logf(fmaxf(s4 * s4 - (sx * sx + sy * sy + sz * sz), EPS_F));
        float lv[4] = {lnkt, lnz, lndelta, lnm2};
#pragma unroll
        for (int f = 0; f < 4; f++)
            rlv[e * 4 + f] = fmaxf(lv[f] * s2l[f] + b2l[f], 0.f);
        vld[e] = A1.w * B1.w;
    }
    __syncthreads();

    if (t < 32) {
        float c = 0.f;
#pragma unroll
        for (int k = 0; k < KK; k++) c += vld[t * 16 + k];
        g_cnt[b * NN + i0 + t] = c;
        cpart[t] = c;
    }

    int nl = t >> 4, c8 = (t & 15) << 3;
    int gi = b * NN + i0 + nl;
    float4 u0 = *(const float4*)(g_u + gi * MSGD + c8);
    float4 u1 = *(const float4*)(g_u + gi * MSGD + c8 + 4);
    float ur[8] = {u0.x, u0.y, u0.z, u0.w, u1.x, u1.y, u1.z, u1.w};
    float wcr[8][4], s3r[8], b3r[8];
#pragma unroll
    for (int q = 0; q < 8; q++) {
        s3r[q] = s3s[c8 + q]; b3r[q] = b3s[c8 + q];
#pragma unroll
        for (int f = 0; f < 4; f++) wcr[q][f] = wc4[(c8 + q) * 5 + f];
    }
    float acc[8] = {0.f, 0.f, 0.f, 0.f, 0.f, 0.f, 0.f, 0.f};
#pragma unroll
    for (int k = 0; k < KK; k++) {
        int e = (nl << 4) | k;
        int j = js[e];
        const float* vp = g_v + (b * NN + j) * MSGD + c8;
        float4 v0 = *(const float4*)vp;
        float4 v1 = *(const float4*)(vp + 4);
        float vr[8] = {v0.x, v0.y, v0.z, v0.w, v1.x, v1.y, v1.z, v1.w};
        float l0 = rlv[e * 4], l1 = rlv[e * 4 + 1], l2 = rlv[e * 4 + 2], l3 = rlv[e * 4 + 3];
        float val = vld[e];
#pragma unroll
        for (int q = 0; q < 8; q++) {
            float h = ur[q] + vr[q] + wcr[q][0] * l0 + wcr[q][1] * l1
                    + wcr[q][2] * l2 + wcr[q][3] * l3;
            acc[q] += fmaxf(h * s3r[q] + b3r[q], 0.f) * val;
        }
    }
    *(float4*)(g_R + gi * MSGD + c8)     = make_float4(acc[0], acc[1], acc[2], acc[3]);
    *(float4*)(g_R + gi * MSGD + c8 + 4) = make_float4(acc[4], acc[5], acc[6], acc[7]);
#pragma unroll
    for (int q = 0; q < 8; q++) R_s[nl * 132 + c8 + q] = acc[q];
    __syncthreads();

    if (t < 128) {
        float s = 0.f;
#pragma unroll
        for (int n = 0; n < 32; n++) s += R_s[n * 132 + t];
        g_Pp[(b * 32 + blk) * MSGD + t] = s;
    }
    if (t == 0) {
        float s = 0.f;
#pragma unroll
        for (int n = 0; n < 32; n++) s += cpart[n];
        g_nbp[b * 32 + blk] = s;
    }
}

// ---------------- k5: slim SE (uses g_M) + GEMM; 64co x 64n, 256 thr, 4 blk/SM ----------------
__global__ void __launch_bounds__(256, 4)
k5_out(const float* __restrict__ w_e2,
       const float* __restrict__ se_w2,
       float* __restrict__ outp) {
    extern __shared__ float sm5[];
    float* w_s = sm5;             // [128 k][68]  this co-half, staged once (34.8KB)
    float* r_s = sm5 + 128 * 68;  // [64 k][68]   64 nodes, staged per k-chunk (17.4KB)
    __shared__ float pooled[128], tv[8], y_s[64];
    __shared__ float nd_s;
    int t   = threadIdx.x;
    int w   = t >> 5, lane = t & 31;
    int h   = blockIdx.x & 1;         // co half
    int nt  = blockIdx.x >> 1;        // node tile (64 nodes)
    int c0  = h * 64;
    int gn0 = nt * 64;
    int b   = gn0 >> 10;
    int nn0 = gn0 & (NN - 1);

    // stage w (once): w_s[k][co] = w_e2[(c0+co)*128 + k]
    for (int q = t; q < 2048; q += 256) {
        int co = q & 63, k4 = (q >> 6) << 2;
        float4 w4 = *(const float4*)(w_e2 + (c0 + co) * 128 + k4);
        w_s[(k4 + 0) * 68 + co] = w4.x;
        w_s[(k4 + 1) * 68 + co] = w4.y;
        w_s[(k4 + 2) * 68 + co] = w4.z;
        w_s[(k4 + 3) * 68 + co] = w4.w;
    }

    // ---- slim SE gate ----
    if (t < 128) {
        float s = 0.f;
#pragma unroll 8
        for (int blk = 0; blk < 32; blk++) s += g_Pp[(b * 32 + blk) * MSGD + t];
        pooled[t] = s;
    }
    if (w == 7) {
        float n = g_nbp[b * 32 + lane];
#pragma unroll
        for (int o = 16; o > 0; o >>= 1) n += __shfl_down_sync(0xffffffffu, n, o);
        if (lane == 0) nd_s = (n == 0.f) ? 1.f : n;
    }
    __syncthreads();
    {
        float s = 0.f;
#pragma unroll
        for (int q = 0; q < 4; q++)
            s += g_M[w * 128 + q * 32 + lane] * pooled[q * 32 + lane];
#pragma unroll
        for (int o = 16; o > 0; o >>= 1) s += __shfl_down_sync(0xffffffffu, s, o);
        if (lane == 0) tv[w] = fmaxf(s / nd_s, 0.f);
    }
    __syncthreads();
    if (t < 64) {
        float z = 0.f;
#pragma unroll
        for (int o = 0; o < 8; o++) z += tv[o] * se_w2[(c0 + t) * 8 + o];
        y_s[t] = 1.f / (1.f + expf(-z));
    }

    // ---- main GEMM: 64 co x 64 n, K=128; per thread 8co x 2n ----
    int cg = w, ng = lane;
    unsigned long long acc[4][2];
#pragma unroll
    for (int i = 0; i < 4; i++)
#pragma unroll
        for (int j = 0; j < 2; j++) acc[i][j] = 0ull;

    for (int k0 = 0; k0 < 128; k0 += 64) {
        for (int q = t; q < 1024; q += 256) {
            int n = q >> 4, k4 = (q & 15) << 2;
            float4 r4 = *(const float4*)(g_R + (gn0 + n) * MSGD + k0 + k4);
            r_s[(k4 + 0) * 68 + n] = r4.x;
            r_s[(k4 + 1) * 68 + n] = r4.y;
            r_s[(k4 + 2) * 68 + n] = r4.z;
            r_s[(k4 + 3) * 68 + n] = r4.w;
        }
        __syncthreads();
#pragma unroll 8
        for (int k = 0; k < 64; k++) {
            const unsigned long long* wp0 =
                (const unsigned long long*)(w_s + (k0 + k) * 68 + cg * 8);
            unsigned long long wp[4] = {wp0[0], wp0[1], wp0[2], wp0[3]};
            float2 r2 = *(const float2*)(r_s + k * 68 + ng * 2);
            unsigned long long rd[2] = {pk2(r2.x, r2.x), pk2(r2.y, r2.y)};
#pragma unroll
            for (int i = 0; i < 4; i++)
#pragma unroll
                for (int j = 0; j < 2; j++) ffma2(acc[i][j], wp[i], rd[j]);
        }
        __syncthreads();
    }

    float yv[8], rcv[2];
#pragma unroll
    for (int i = 0; i < 8; i++) yv[i] = y_s[cg * 8 + i];
#pragma unroll
    for (int j = 0; j < 2; j++)
        rcv[j] = 1.f / fmaxf(g_cnt[b * NN + nn0 + ng * 2 + j], 1.f);

    float vals[8][2];
#pragma unroll
    for (int i = 0; i < 4; i++)
#pragma unroll
        for (int j = 0; j < 2; j++) {
            float lo, hi;
            upk2(acc[i][j], lo, hi);
            vals[2 * i][j] = lo; vals[2 * i + 1][j] = hi;
        }
#pragma unroll
    for (int i = 0; i < 8; i++) {
        float sc = yv[i];
        float* op = outp + (b * 128 + c0 + cg * 8 + i) * NN + nn0 + ng * 2;
        *(float2*)op = make_float2(vals[i][0] * sc * rcv[0], vals[i][1] * sc * rcv[1]);
    }
}

extern "C" void kernel_launch(void* const* d_in, const int* in_sizes, int n_in,
                              void* d_out, int out_size) {
    const float* pts   = (const float*)d_in[0];
    const float* fts   = (const float*)d_in[1];
    const float* lvs   = (const float*)d_in[2];
    const void*  mask  = d_in[3];
    const float* bn1_s = (const float*)d_in[4];
    const float* bn1_b = (const float*)d_in[5];
    const float* w_node= (const float*)d_in[6];
    const float* bn2_s = (const float*)d_in[7];
    const float* bn2_b = (const float*)d_in[8];
    const float* w_e1  = (const float*)d_in[9];
    const float* bn3_s = (const float*)d_in[10];
    const float* bn3_b = (const float*)d_in[11];
    const float* w_e2  = (const float*)d_in[12];
    const float* se_w1 = (const float*)d_in[13];
    const float* se_w2 = (const float*)d_in[14];
    float* outp = (float*)d_out;

    cudaFuncSetAttribute(k3_nodeuv, cudaFuncAttributeMaxDynamicSharedMemorySize, 69632);
    // k5 smem: (128+64)*68 floats = 13056 floats = 52224 B ; x4 blocks = 209KB <= 228KB
    cudaFuncSetAttribute(k5_out,    cudaFuncAttributeMaxDynamicSharedMemorySize, 52224);

    kA_prep_knn<<<1024, 256>>>(pts, lvs, mask, se_w1, w_e2);
    k3_nodeuv<<<256, 256, 69632>>>(fts, bn1_s, bn1_b, w_node, bn2_s, bn2_b, w_e1);
    k4_edge<<<512, 512>>>(w_e1, bn2_s, bn2_b, bn3_s, bn3_b);
    k5_out<<<512, 256, 52224>>>(w_e2, se_w2, outp);
}

// round 17
// speedup vs baseline: 1.0706x; 1.0706x over previous
#include <cuda_runtime.h>
#include <math.h>
#include <float.h>

#define BB 16
#define NN 1024
#define KK 16
#define MSGD 128
#define PI_F 3.14159265358979323846f
#define TWOPI_F 6.28318530717958647692f
#define INV_TWOPI_F 0.15915494309189533577f
#define EPS_F 1e-8f

// ---------------- device scratch ----------------
__device__ __align__(16) float g_lvpack[BB*NN*8];   // px,py,pz,e,pt,rap,phi,mask
__device__ int   g_idx[BB*NN*KK];
__device__ __align__(16) float g_u[BB*NN*MSGD];
__device__ __align__(16) float g_v[BB*NN*MSGD];
__device__ __align__(16) float g_R[BB*NN*MSGD];
__device__ __align__(16) float g_cnt[BB*NN];
__device__ float g_Pp[BB*32*MSGD];
__device__ float g_nbp[BB*32];
__device__ float g_M[8*128];                        // se_w1 @ w_e2 (precomputed)

__device__ __forceinline__ float wrap_dphi(float x) {
    float xp = x + PI_F;
    return xp - floorf(xp * INV_TWOPI_F) * TWOPI_F - PI_F;
}

// packed f32x2 helpers
__device__ __forceinline__ unsigned long long pk2(float lo, float hi) {
    unsigned long long r;
    asm("mov.b64 %0, {%1, %2};" : "=l"(r) : "f"(lo), "f"(hi));
    return r;
}
__device__ __forceinline__ void upk2(unsigned long long v, float& lo, float& hi) {
    asm("mov.b64 {%0, %1}, %2;" : "=f"(lo), "=f"(hi) : "l"(v));
}
__device__ __forceinline__ void ffma2(unsigned long long& acc,
                                      unsigned long long a, unsigned long long b) {
    asm("fma.rn.f32x2 %0, %1, %2, %0;" : "+l"(acc) : "l"(a), "l"(b));
}

// ---------------- kA: mask detect + lv prep + knn (bitonic warm-up + stale-thr pops) ----------------
__global__ void __launch_bounds__(256, 6)
kA_prep_knn(const float* __restrict__ pts, const float* __restrict__ lvs,
            const void* __restrict__ mask,
            const float* __restrict__ se_w1, const float* __restrict__ w_e2) {
    __shared__ float se[NN], sp[NN];
    __shared__ int s_mode;
    int t = threadIdx.x;
    int b = blockIdx.x >> 6;
    int chunk = blockIdx.x & 63;          // 16 nodes per block

    // block 0: precompute M = se_w1 @ w_e2 (weights-only, 8x128)
    if (blockIdx.x == 0) {
        int k = t & 127, ih = t >> 7;
#pragma unroll
        for (int ii = 0; ii < 4; ii++) {
            int i = ih * 4 + ii;
            float s = 0.f;
#pragma unroll 4
            for (int c = 0; c < 128; c++)
                s += se_w1[i * 128 + c] * w_e2[c * 128 + k];
            g_M[i * 128 + k] = s;
        }
    }

    if (t == 0) {
        const unsigned int* mw = (const unsigned int*)mask;
        int allf = 1, alli = 1;
        for (int q = 0; q < 64; q++) {
            unsigned int wv = mw[q];
            if (!(wv == 0u || wv == 0x3F800000u)) allf = 0;
            if (!(wv == 0u || wv == 1u))          alli = 0;
        }
        s_mode = allf ? 0 : (alli ? 1 : 2);
    }
    for (int q = t; q < NN; q += 256) {
        se[q] = pts[b * 2 * NN + q];
        sp[q] = pts[b * 2 * NN + NN + q];
    }
    __syncthreads();

    if (t < 16) {
        int gid = b * NN + chunk * 16 + t;
        int n = gid & (NN - 1);
        int mode = s_mode;
        float m;
        if (mode == 0)      m = (((const float*)mask)[gid] != 0.f) ? 1.f : 0.f;
        else if (mode == 1) m = (((const int*)mask)[gid] != 0) ? 1.f : 0.f;
        else                m = (((const unsigned char*)mask)[gid] != 0) ? 1.f : 0.f;
        const float* base = lvs + b * 4 * NN + n;
        float px = base[0], py = base[NN], pz = base[2 * NN], e = base[3 * NN];
        float pt  = sqrtf(px * px + py * py);
        float rap = 0.5f * log1pf(2.f * pz / fmaxf(e - pz, 1e-20f));
        float phi = atan2f(py, px);
        float4* o = (float4*)(g_lvpack + gid * 8);
        o[0] = make_float4(px, py, pz, e);
        o[1] = make_float4(pt, rap, phi, m);
    }

    int w = t >> 5, lane = t & 31;
#pragma unroll 1
    for (int nn = 0; nn < 2; nn++) {
        int i = chunk * 16 + w * 2 + nn;
        float ei = se[i], pii = sp[i];

        // --- warm-up: bitonic sort first 32 candidates by (d, j) lex ascending ---
        float d;
        int   jv = lane;
        {
            float de = ei - se[lane];
            float dp = wrap_dphi(pii - sp[lane]);
            d = de * de + dp * dp;
        }
#pragma unroll
        for (int kk = 2; kk <= 32; kk <<= 1) {
#pragma unroll
            for (int jj = kk >> 1; jj > 0; jj >>= 1) {
                float od = __shfl_xor_sync(0xffffffffu, d, jj);
                int   oj = __shfl_xor_sync(0xffffffffu, jv, jj);
                bool up = ((lane & kk) == 0);
                bool lower = ((lane & jj) == 0);
                bool smaller = (od < d) || (od == d && oj < jv);
                bool keepOther = (up == lower) ? smaller : !smaller;
                if (keepOther) { d = od; jv = oj; }
            }
        }
        float dslot = d;      // lanes 0..31 sorted ascending; only 0..15 matter
        int   jslot = jv;
        float thr = __shfl_sync(0xffffffffu, dslot, 15);

        // --- main scan; thr held constant within each 32-candidate batch ---
#pragma unroll 1
        for (int j0 = 32; j0 < NN; j0 += 32) {
            int j = j0 + lane;
            float de = ei - se[j];
            float dp = wrap_dphi(pii - sp[j]);
            float dd = de * de + dp * dp;
            unsigned m = __ballot_sync(0xffffffffu, dd < thr);
            if (m) {
                do {
                    int src = __ffs(m) - 1; m &= m - 1;
                    float dv = __shfl_sync(0xffffffffu, dd, src);
                    int jn = j0 + src;
                    float prevd = __shfl_up_sync(0xffffffffu, dslot, 1);
                    int   prevj = __shfl_up_sync(0xffffffffu, jslot, 1);
                    bool pg = (lane > 0) && (prevd > dv);
                    if (dslot > dv) {
                        dslot = pg ? prevd : dv;
                        jslot = pg ? prevj : jn;
                    }
                } while (m);
                thr = __shfl_sync(0xffffffffu, dslot, 15);
            }
        }
        if (lane < 16) g_idx[(b * NN + i) * KK + lane] = jslot;
    }
}

// ---------------- k3: node features -> u, v (64 nodes/block, 2 blocks/SM) ----------------
__global__ void __launch_bounds__(256, 2)
k3_nodeuv(const float* __restrict__ fts,
          const float* __restrict__ bn1_s, const float* __restrict__ bn1_b,
          const float* __restrict__ w_node,
          const float* __restrict__ bn2_s, const float* __restrict__ bn2_b,
          const float* __restrict__ w_e1) {
    extern __shared__ float sm3[];
    float* ra_s = sm3;               // [64 k][68]
    float* rb_s = ra_s + 64 * 68;    // [64 k][68]
    float* w_s  = rb_s + 64 * 68;    // [64 k][132]; phase-1 overlay:
    float* a_s  = w_s;               // [32 c][64 n]
    float* wn_s = w_s + 2048;        // [64 o][32 c]

    int t   = threadIdx.x;
    int gn0 = blockIdx.x * 64;
    int b   = gn0 >> 10;
    int n0  = gn0 & (NN - 1);

    for (int q = t; q < 2048; q += 256) {
        int c = q >> 6, n = q & 63;
        float v = fts[(b * 32 + c) * NN + n0 + n];
        a_s[q] = fmaxf(v * __ldg(bn1_s + c) + __ldg(bn1_b + c), 0.f);
    }
    for (int q = t; q < 2048; q += 256) wn_s[q] = w_node[q];
    __syncthreads();

    {
        int og = t >> 6, node = t & 63;
        float av[32];
#pragma unroll
        for (int c = 0; c < 32; c++) av[c] = a_s[c * 64 + node];
#pragma unroll
        for (int oo = 0; oo < 16; oo++) {
            int o = og * 16 + oo;
            const float* wr = wn_s + o * 32;
            float nv = 0.f;
#pragma unroll
            for (int c = 0; c < 32; c++) nv += wr[c] * av[c];
            ra_s[o * 68 + node] = fmaxf(nv * __ldg(bn2_s + o)      + __ldg(bn2_b + o), 0.f);
            rb_s[o * 68 + node] = fmaxf(nv * __ldg(bn2_s + 64 + o) + __ldg(bn2_b + 64 + o), 0.f);
        }
    }
    __syncthreads();

    int cg = t >> 4, ng = t & 15;
#pragma unroll
    for (int pass = 0; pass < 2; pass++) {
        const float* rs = pass ? rb_s : ra_s;
        float* gout = pass ? g_v : g_u;
        for (int q = t; q < 2048; q += 256) {
            int ch = q >> 4, k4 = (q & 15) << 2;
            float4 w4 = *(const float4*)(w_e1 + ch * 132 + pass * 64 + k4);
            w_s[(k4 + 0) * 132 + ch] = w4.x;
            w_s[(k4 + 1) * 132 + ch] = w4.y;
            w_s[(k4 + 2) * 132 + ch] = w4.z;
            w_s[(k4 + 3) * 132 + ch] = w4.w;
        }
        __syncthreads();
        unsigned long long acc[4][4];
#pragma unroll
        for (int i = 0; i < 4; i++)
#pragma unroll
            for (int j = 0; j < 4; j++) acc[i][j] = 0ull;
#pragma unroll 4
        for (int k = 0; k < 64; k++) {
            float4 wa = *(const float4*)(w_s + k * 132 + cg * 8);
            float4 wb = *(const float4*)(w_s + k * 132 + cg * 8 + 4);
            float4 r4 = *(const float4*)(rs  + k * 68 + ng * 4);
            unsigned long long wp[4] = {pk2(wa.x, wa.y), pk2(wa.z, wa.w),
                                        pk2(wb.x, wb.y), pk2(wb.z, wb.w)};
            unsigned long long rd[4] = {pk2(r4.x, r4.x), pk2(r4.y, r4.y),
                                        pk2(r4.z, r4.z), pk2(r4.w, r4.w)};
#pragma unroll
            for (int i = 0; i < 4; i++)
#pragma unroll
                for (int j = 0; j < 4; j++) ffma2(acc[i][j], wp[i], rd[j]);
        }
#pragma unroll
        for (int j = 0; j < 4; j++) {
            float v0, v1, v2, v3, v4, v5, v6, v7;
            upk2(acc[0][j], v0, v1); upk2(acc[1][j], v2, v3);
            upk2(acc[2][j], v4, v5); upk2(acc[3][j], v6, v7);
            float* op = gout + (gn0 + ng * 4 + j) * MSGD + cg * 8;
            *(float4*)op       = make_float4(v0, v1, v2, v3);
            *(float4*)(op + 4) = make_float4(v4, v5, v6, v7);
        }
        __syncthreads();
    }
}

// ---------------- k4: fused edge kernel -> R + block-partial pool ----------------
__global__ void __launch_bounds__(512)
k4_edge(const float* __restrict__ w_e1,
        const float* __restrict__ bn2_s, const float* __restrict__ bn2_b,
        const float* __restrict__ bn3_s, const float* __restrict__ bn3_b) {
    __shared__ int   js[512];
    __shared__ float rlv[512 * 4];
    __shared__ float vld[512];
    __shared__ float wc4[128 * 5];
    __shared__ float s3s[128], b3s[128];
    __shared__ float s2l[4], b2l[4];
    __shared__ float R_s[32 * 132];
    __shared__ float cpart[32];
    int t  = threadIdx.x;
    int b  = blockIdx.x >> 5;
    int blk = blockIdx.x & 31;
    int i0 = blk * 32;

    js[t] = g_idx[(b * NN + i0) * KK + t];
    if (t < 128) {
#pragma unroll
        for (int f = 0; f < 4; f++) wc4[t * 5 + f] = w_e1[t * 132 + 128 + f];
        s3s[t] = bn3_s[t]; b3s[t] = bn3_b[t];
    }
    if (t < 4) { s2l[t] = bn2_s[128 + t]; b2l[t] = bn2_b[128 + t]; }
    __syncthreads();

    {
        int e = t;
        int i = i0 + (e >> 4), j = js[e];
        const float4* Li = (const float4*)(g_lvpack + (b * NN + i) * 8);
        const float4* Lj = (const float4*)(g_lvpack + (b * NN + j) * 8);
        float4 A0 = Li[0], A1 = Li[1], B0 = Lj[0], B1 = Lj[1];
        float pti = A1.x, ptj = B1.x;
        float ptmin = fminf(pti, ptj);
        float dphi = wrap_dphi(A1.z - B1.z);
        float drap  = A1.y - B1.y;
        float delta = sqrtf(drap * drap + dphi * dphi);
        float lndelta = logf(fmaxf(delta, EPS_F));
        float lnkt    = logf(fmaxf(ptmin * delta, EPS_F));
        float lnz     = logf(fmaxf(ptmin / fmaxf(pti + ptj, EPS_F), EPS_F));
        float sx = A0.x + B0.x, sy = A0.y + B0.y, sz = A0.z + B0.z, s4 = A0.w + B0.w;
        float lnm2 = logf(fmaxf(s4 * s4 - (sx * sx + sy * sy + sz * sz), EPS_F));
        float lv[4] = {lnkt, lnz, lndelta, lnm2};
#pragma unroll
        for (int f = 0; f < 4; f++)
            rlv[e * 4 + f] = fmaxf(lv[f] * s2l[f] + b2l[f], 0.f);
        vld[e] = A1.w * B1.w;
    }
    __syncthreads();

    if (t < 32) {
        float c = 0.f;
#pragma unroll
        for (int k = 0; k < KK; k++) c += vld[t * 16 + k];
        g_cnt[b * NN + i0 + t] = c;
        cpart[t] = c;
    }

    int nl = t >> 4, c8 = (t & 15) << 3;
    int gi = b * NN + i0 + nl;
    float4 u0 = *(const float4*)(g_u + gi * MSGD + c8);
    float4 u1 = *(const float4*)(g_u + gi * MSGD + c8 + 4);
    float ur[8] = {u0.x, u0.y, u0.z, u0.w, u1.x, u1.y, u1.z, u1.w};
    float wcr[8][4], s3r[8], b3r[8];
#pragma unroll
    for (int q = 0; q < 8; q++) {
        s3r[q] = s3s[c8 + q]; b3r[q] = b3s[c8 + q];
#pragma unroll
        for (int f = 0; f < 4; f++) wcr[q][f] = wc4[(c8 + q) * 5 + f];
    }
    float acc[8] = {0.f, 0.f, 0.f, 0.f, 0.f, 0.f, 0.f, 0.f};
#pragma unroll
    for (int k = 0; k < KK; k++) {
        int e = (nl << 4) | k;
        int j = js[e];
        const float* vp = g_v + (b * NN + j) * MSGD + c8;
        float4 v0 = *(const float4*)vp;
        float4 v1 = *(const float4*)(vp + 4);
        float vr[8] = {v0.x, v0.y, v0.z, v0.w, v1.x, v1.y, v1.z, v1.w};
        float l0 = rlv[e * 4], l1 = rlv[e * 4 + 1], l2 = rlv[e * 4 + 2], l3 = rlv[e * 4 + 3];
        float val = vld[e];
#pragma unroll
        for (int q = 0; q < 8; q++) {
            float h = ur[q] + vr[q] + wcr[q][0] * l0 + wcr[q][1] * l1
                    + wcr[q][2] * l2 + wcr[q][3] * l3;
            acc[q] += fmaxf(h * s3r[q] + b3r[q], 0.f) * val;
        }
    }
    *(float4*)(g_R + gi * MSGD + c8)     = make_float4(acc[0], acc[1], acc[2], acc[3]);
    *(float4*)(g_R + gi * MSGD + c8 + 4) = make_float4(acc[4], acc[5], acc[6], acc[7]);
#pragma unroll
    for (int q = 0; q < 8; q++) R_s[nl * 132 + c8 + q] = acc[q];
    __syncthreads();

    if (t < 128) {
        float s = 0.f;
#pragma unroll
        for (int n = 0; n < 32; n++) s += R_s[n * 132 + t];
        g_Pp[(b * 32 + blk) * MSGD + t] = s;
    }
    if (t == 0) {
        float s = 0.f;
#pragma unroll
        for (int n = 0; n < 32; n++) s += cpart[n];
        g_nbp[b * 32 + blk] = s;
    }
}

// ---------------- k5: slim SE (uses g_M) + GEMM; 64co x 128n, 256 thr ----------------
__global__ void __launch_bounds__(256, 3)
k5_out(const float* __restrict__ w_e2,
       const float* __restrict__ se_w2,
       float* __restrict__ outp) {
    extern __shared__ float sm5[];
    float* w_s = sm5;             // [128 k][68]
    float* r_s = sm5 + 128 * 68;  // [64 k][132]
    __shared__ float pooled[128], tv[8], y_s[64];
    __shared__ float nd_s;
    int t   = threadIdx.x;
    int w   = t >> 5, lane = t & 31;
    int h   = blockIdx.x & 1;
    int nt  = blockIdx.x >> 1;
    int c0  = h * 64;
    int gn0 = nt * 128;
    int b   = gn0 >> 10;
    int nn0 = gn0 & (NN - 1);

    for (int q = t; q < 2048; q += 256) {
        int co = q & 63, k4 = (q >> 6) << 2;
        float4 w4 = *(const float4*)(w_e2 + (c0 + co) * 128 + k4);
        w_s[(k4 + 0) * 68 + co] = w4.x;
        w_s[(k4 + 1) * 68 + co] = w4.y;
        w_s[(k4 + 2) * 68 + co] = w4.z;
        w_s[(k4 + 3) * 68 + co] = w4.w;
    }

    if (t < 128) {
        float s = 0.f;
#pragma unroll 8
        for (int blk = 0; blk < 32; blk++) s += g_Pp[(b * 32 + blk) * MSGD + t];
        pooled[t] = s;
    }
    if (w == 7) {
        float n = g_nbp[b * 32 + lane];
#pragma unroll
        for (int o = 16; o > 0; o >>= 1) n += __shfl_down_sync(0xffffffffu, n, o);
        if (lane == 0) nd_s = (n == 0.f) ? 1.f : n;
    }
    __syncthreads();
    {
        float s = 0.f;
#pragma unroll
        for (int q = 0; q < 4; q++)
            s += g_M[w * 128 + q * 32 + lane] * pooled[q * 32 + lane];
#pragma unroll
        for (int o = 16; o > 0; o >>= 1) s += __shfl_down_sync(0xffffffffu, s, o);
        if (lane == 0) tv[w] = fmaxf(s / nd_s, 0.f);
    }
    __syncthreads();
    if (t < 64) {
        float z = 0.f;
#pragma unroll
        for (int o = 0; o < 8; o++) z += tv[o] * se_w2[(c0 + t) * 8 + o];
        y_s[t] = 1.f / (1.f + expf(-z));
    }

    int cg = w, ng = lane;
    unsigned long long acc[4][4];
#pragma unroll
    for (int i = 0; i < 4; i++)
#pragma unroll
        for (int j = 0; j < 4; j++) acc[i][j] = 0ull;

    for (int k0 = 0; k0 < 128; k0 += 64) {
        for (int q = t; q < 2048; q += 256) {
            int n = q >> 4, k4 = (q & 15) << 2;
            float4 r4 = *(const float4*)(g_R + (gn0 + n) * MSGD + k0 + k4);
            r_s[(k4 + 0) * 132 + n] = r4.x;
            r_s[(k4 + 1) * 132 + n] = r4.y;
            r_s[(k4 + 2) * 132 + n] = r4.z;
            r_s[(k4 + 3) * 132 + n] = r4.w;
        }
        __syncthreads();
#pragma unroll 4
        for (int k = 0; k < 64; k++) {
            const unsigned long long* wp0 =
                (const unsigned long long*)(w_s + (k0 + k) * 68 + cg * 8);
            unsigned long long wp[4] = {wp0[0], wp0[1], wp0[2], wp0[3]};
            float4 r4 = *(const float4*)(r_s + k * 132 + ng * 4);
            unsigned long long rd[4] = {pk2(r4.x, r4.x), pk2(r4.y, r4.y),
                                        pk2(r4.z, r4.z), pk2(r4.w, r4.w)};
#pragma unroll
            for (int i = 0; i < 4; i++)
#pragma unroll
                for (int j = 0; j < 4; j++) ffma2(acc[i][j], wp[i], rd[j]);
        }
        __syncthreads();
    }

    float yv[8], rcv[4];
#pragma unroll
    for (int i = 0; i < 8; i++) yv[i] = y_s[cg * 8 + i];
#pragma unroll
    for (int j = 0; j < 4; j++)
        rcv[j] = 1.f / fmaxf(g_cnt[b * NN + nn0 + ng * 4 + j], 1.f);

    float vals[8][4];
#pragma unroll
    for (int i = 0; i < 4; i++)
#pragma unroll
        for (int j = 0; j < 4; j++) {
            float lo, hi;
            upk2(acc[i][j], lo, hi);
            vals[2 * i][j] = lo; vals[2 * i + 1][j] = hi;
        }
#pragma unroll
    for (int i = 0; i < 8; i++) {
        float sc = yv[i];
        float* op = outp + (b * 128 + c0 + cg * 8 + i) * NN + nn0 + ng * 4;
        *(float4*)op = make_float4(vals[i][0] * sc * rcv[0], vals[i][1] * sc * rcv[1],
                                   vals[i][2] * sc * rcv[2], vals[i][3] * sc * rcv[3]);
    }
}

extern "C" void kernel_launch(void* const* d_in, const int* in_sizes, int n_in,
                              void* d_out, int out_size) {
    const float* pts   = (const float*)d_in[0];
    const float* fts   = (const float*)d_in[1];
    const float* lvs   = (const float*)d_in[2];
    const void*  mask  = d_in[3];
    const float* bn1_s = (const float*)d_in[4];
    const float* bn1_b = (const float*)d_in[5];
    const float* w_node= (const float*)d_in[6];
    const float* bn2_s = (const float*)d_in[7];
    const float* bn2_b = (const float*)d_in[8];
    const float* w_e1  = (const float*)d_in[9];
    const float* bn3_s = (const float*)d_in[10];
    const float* bn3_b = (const float*)d_in[11];
    const float* w_e2  = (const float*)d_in[12];
    const float* se_w1 = (const float*)d_in[13];
    const float* se_w2 = (const float*)d_in[14];
    float* outp = (float*)d_out;

    cudaFuncSetAttribute(k3_nodeuv, cudaFuncAttributeMaxDynamicSharedMemorySize, 69632);
    cudaFuncSetAttribute(k5_out,    cudaFuncAttributeMaxDynamicSharedMemorySize, 68608);

    kA_prep_knn<<<1024, 256>>>(pts, lvs, mask, se_w1, w_e2);
    k3_nodeuv<<<256, 256, 69632>>>(fts, bn1_s, bn1_b, w_node, bn2_s, bn2_b, w_e1);
    k4_edge<<<512, 512>>>(w_e1, bn2_s, bn2_b, bn3_s, bn3_b);
    k5_out<<<256, 256, 68608>>>(w_e2, se_w2, outp);
}